// round 2
// baseline (speedup 1.0000x reference)
#include <cuda_runtime.h>
#include <math.h>

#define Tt 512
#define Bb 64
#define Hh 1024
#define G4 4096   // 4*H gate outputs
#define K2 2048   // 2*H input features

// Scratch (device globals — no runtime allocation allowed)
__device__ float g_W[(size_t)G4 * K2];            // packed [4096][2048]: rows gate-major
__device__ float g_bias[G4];
__device__ float g_gx[(size_t)Tt * Bb * G4];      // x @ Wx^T + b, precomputed for all t (512MB)
__device__ float g_h[2][Bb * Hh];                 // double-buffered hidden state
__device__ float g_c[Bb * Hh];                    // cell state

// ---------------------------------------------------------------------------
// Repack weights: W[j][k], j = gate*1024 + unit, k in [0,2048)
// ---------------------------------------------------------------------------
__global__ void repack_kernel(const float* __restrict__ Wi, const float* __restrict__ Wf,
                              const float* __restrict__ Wc, const float* __restrict__ Wo,
                              const float* __restrict__ bi, const float* __restrict__ bf,
                              const float* __restrict__ bc, const float* __restrict__ bo) {
    size_t total  = (size_t)G4 * K2;
    size_t stride = (size_t)gridDim.x * blockDim.x;
    for (size_t idx = (size_t)blockIdx.x * blockDim.x + threadIdx.x; idx < total; idx += stride) {
        int j = (int)(idx / K2);
        int k = (int)(idx % K2);
        int g = j >> 10, u = j & 1023;
        const float* src = (g == 0) ? Wi : (g == 1) ? Wf : (g == 2) ? Wc : Wo;
        g_W[idx] = src[(size_t)u * K2 + k];
    }
    for (int j = blockIdx.x * blockDim.x + threadIdx.x; j < G4; j += (int)stride) {
        int g = j >> 10, u = j & 1023;
        const float* sb = (g == 0) ? bi : (g == 1) ? bf : (g == 2) ? bc : bo;
        g_bias[j] = sb[u];
    }
}

__global__ void init_hc_kernel() {
    int i = blockIdx.x * blockDim.x + threadIdx.x;
    if (i < Bb * Hh) { g_h[0][i] = 0.0f; g_c[i] = 0.0f; }
}

// ---------------------------------------------------------------------------
// Big batched GEMM: g_gx[m][n] = sum_k x[m][k] * W[n][k]  + bias[n]
//   m = t*64 + b (32768 rows), n in [0,4096), k in [0,1024)
// Tile 128x128, 256 threads, 8x8 register blocking (split 4+4 for LDS.128).
// ---------------------------------------------------------------------------
__global__ __launch_bounds__(256) void gemm_x_kernel(const float* __restrict__ x) {
    __shared__ float As[16][128];
    __shared__ float Bs[16][128];
    const int tid = threadIdx.x;
    const int m0 = blockIdx.y * 128;
    const int n0 = blockIdx.x * 128;
    const int mw = tid >> 4;   // 0..15
    const int nw = tid & 15;   // 0..15

    float acc[8][8];
#pragma unroll
    for (int i = 0; i < 8; i++)
#pragma unroll
        for (int j = 0; j < 8; j++) acc[i][j] = 0.0f;

    for (int k0 = 0; k0 < Hh; k0 += 16) {
        __syncthreads();
#pragma unroll
        for (int r = 0; r < 2; r++) {
            int id  = tid + r * 256;
            int mm  = id >> 2;
            int kq4 = (id & 3) * 4;
            float4 v = *reinterpret_cast<const float4*>(x + (size_t)(m0 + mm) * Hh + k0 + kq4);
            As[kq4 + 0][mm] = v.x; As[kq4 + 1][mm] = v.y;
            As[kq4 + 2][mm] = v.z; As[kq4 + 3][mm] = v.w;
            float4 w = *reinterpret_cast<const float4*>(g_W + (size_t)(n0 + mm) * K2 + k0 + kq4);
            Bs[kq4 + 0][mm] = w.x; Bs[kq4 + 1][mm] = w.y;
            Bs[kq4 + 2][mm] = w.z; Bs[kq4 + 3][mm] = w.w;
        }
        __syncthreads();
#pragma unroll
        for (int kk = 0; kk < 16; kk++) {
            float a[8], b[8];
            *(float4*)(a)     = *(const float4*)(&As[kk][mw * 4]);
            *(float4*)(a + 4) = *(const float4*)(&As[kk][64 + mw * 4]);
            *(float4*)(b)     = *(const float4*)(&Bs[kk][nw * 4]);
            *(float4*)(b + 4) = *(const float4*)(&Bs[kk][64 + nw * 4]);
#pragma unroll
            for (int i = 0; i < 8; i++)
#pragma unroll
                for (int j = 0; j < 8; j++)
                    acc[i][j] = fmaf(a[i], b[j], acc[i][j]);
        }
    }

#pragma unroll
    for (int i = 0; i < 8; i++) {
        int mloc = (i < 4) ? (mw * 4 + i) : (64 + mw * 4 + (i - 4));
        float* orow = g_gx + (size_t)(m0 + mloc) * G4 + n0;
#pragma unroll
        for (int j = 0; j < 8; j++) {
            int nloc = (j < 4) ? (nw * 4 + j) : (64 + nw * 4 + (j - 4));
            orow[nloc] = acc[i][j] + g_bias[n0 + nloc];
        }
    }
}

// ---------------------------------------------------------------------------
// Fused recurrent step: gates_h = h @ Wh^T, add precomputed gx, activations,
// update c and h, write hidden_seq[t].
// 128 blocks x 128 threads. Block bu owns hidden units [bu*8, bu*8+8) for
// all 4 gates (32 weight rows), all 64 batch rows. Thread: 4M x 4gates tile.
// ---------------------------------------------------------------------------
__device__ __forceinline__ float sigf(float v) { return 1.0f / (1.0f + __expf(-v)); }
__device__ __forceinline__ float tanh_fast(float v) {
    float e = __expf(-2.0f * fabsf(v));
    float r = (1.0f - e) / (1.0f + e);
    return (v >= 0.0f) ? r : -r;
}

__global__ __launch_bounds__(128) void lstm_step_kernel(int t, float* __restrict__ out_seq) {
    __shared__ float hs[16][64];
    __shared__ float ws[16][32];
    const int tid  = threadIdx.x;
    const int bu   = blockIdx.x;     // unit group: u0 = bu*8
    const int n4   = tid & 7;        // unit within group
    const int mgrp = tid >> 3;       // 0..15 ; m = mgrp*4 + i
    const float* __restrict__ h_in = g_h[t & 1];
    float* __restrict__ h_out      = g_h[(t + 1) & 1];

    float acc[4][4];
#pragma unroll
    for (int i = 0; i < 4; i++)
#pragma unroll
        for (int j = 0; j < 4; j++) acc[i][j] = 0.0f;

    // Wh row base for this thread's loader lane
    const int nn   = tid >> 2;                       // 0..31
    const int lkq4 = (tid & 3) * 4;
    const size_t wrow = ((size_t)(nn >> 3) * Hh + bu * 8 + (nn & 7)) * K2 + Hh;

    for (int k0 = 0; k0 < Hh; k0 += 16) {
        __syncthreads();
#pragma unroll
        for (int r = 0; r < 2; r++) {
            int id  = tid + r * 128;
            int mm  = id >> 2;
            int kq4 = (id & 3) * 4;
            float4 v = *reinterpret_cast<const float4*>(h_in + mm * Hh + k0 + kq4);
            hs[kq4 + 0][mm] = v.x; hs[kq4 + 1][mm] = v.y;
            hs[kq4 + 2][mm] = v.z; hs[kq4 + 3][mm] = v.w;
        }
        {
            float4 w = *reinterpret_cast<const float4*>(g_W + wrow + k0 + lkq4);
            ws[lkq4 + 0][nn] = w.x; ws[lkq4 + 1][nn] = w.y;
            ws[lkq4 + 2][nn] = w.z; ws[lkq4 + 3][nn] = w.w;
        }
        __syncthreads();
#pragma unroll
        for (int kk = 0; kk < 16; kk++) {
            float a[4];
            *(float4*)a = *(const float4*)(&hs[kk][mgrp * 4]);
            float b0 = ws[kk][n4];
            float b1 = ws[kk][n4 + 8];
            float b2 = ws[kk][n4 + 16];
            float b3 = ws[kk][n4 + 24];
#pragma unroll
            for (int i = 0; i < 4; i++) {
                acc[i][0] = fmaf(a[i], b0, acc[i][0]);
                acc[i][1] = fmaf(a[i], b1, acc[i][1]);
                acc[i][2] = fmaf(a[i], b2, acc[i][2]);
                acc[i][3] = fmaf(a[i], b3, acc[i][3]);
            }
        }
    }

    const int u = bu * 8 + n4;
#pragma unroll
    for (int i = 0; i < 4; i++) {
        int m = mgrp * 4 + i;
        size_t gxb = ((size_t)t * Bb + m) * G4 + u;
        float xi = g_gx[gxb]        + acc[i][0];
        float xf = g_gx[gxb + 1024] + acc[i][1];
        float xg = g_gx[gxb + 2048] + acc[i][2];
        float xo = g_gx[gxb + 3072] + acc[i][3];
        float it = sigf(xi);
        float ft = sigf(xf);
        float gt = tanh_fast(xg);
        float ot = sigf(xo);
        int hc = m * Hh + u;
        float cn = fmaf(ft, g_c[hc], it * gt);
        g_c[hc] = cn;
        float hn = ot * tanh_fast(cn);
        h_out[hc] = hn;
        out_seq[(size_t)t * (Bb * Hh) + hc] = hn;
    }
}

__global__ void finalize_kernel(float* __restrict__ out) {
    int i = blockIdx.x * blockDim.x + threadIdx.x;
    if (i < Bb * Hh) {
        size_t base = (size_t)Tt * Bb * Hh;
        out[base + i]           = g_h[Tt & 1][i];   // h_T
        out[base + Bb * Hh + i] = g_c[i];           // c_T
    }
}

// ---------------------------------------------------------------------------
extern "C" void kernel_launch(void* const* d_in, const int* in_sizes, int n_in,
                              void* d_out, int out_size) {
    const float* x  = (const float*)d_in[0];
    const float* Wi = (const float*)d_in[1];
    const float* bi = (const float*)d_in[2];
    const float* Wf = (const float*)d_in[3];
    const float* bf = (const float*)d_in[4];
    const float* Wc = (const float*)d_in[5];
    const float* bc = (const float*)d_in[6];
    const float* Wo = (const float*)d_in[7];
    const float* bo = (const float*)d_in[8];
    float* out = (float*)d_out;

    repack_kernel<<<512, 256>>>(Wi, Wf, Wc, Wo, bi, bf, bc, bo);
    init_hc_kernel<<<(Bb * Hh + 255) / 256, 256>>>();

    // Precompute x-part of all gates: one big GEMM [32768 x 4096 x 1024]
    gemm_x_kernel<<<dim3(G4 / 128, (Tt * Bb) / 128), 256>>>(x);

    // Sequential recurrence
    for (int t = 0; t < Tt; t++) {
        lstm_step_kernel<<<128, 128>>>(t, out);
    }

    finalize_kernel<<<(Bb * Hh + 255) / 256, 256>>>(out);
}

// round 4
// speedup vs baseline: 1.3514x; 1.3514x over previous
#include <cuda_runtime.h>
#include <cuda_bf16.h>
#include <cstdint>
#include <math.h>

#define Tt 512
#define Bb 64
#define Hh 1024
#define G4 4096
#define K2 2048

// ---------------------------------------------------------------------------
// Device globals (no runtime allocation allowed).
// Weight-derived arrays are UNIT-MAJOR: row j = u*4 + g, g in {i,f,c,o}.
// ---------------------------------------------------------------------------
__device__ __nv_bfloat16 g_x_hi[(size_t)Tt * Bb * Hh];
__device__ __nv_bfloat16 g_x_lo[(size_t)Tt * Bb * Hh];
__device__ __nv_bfloat16 g_Wx_hi[(size_t)G4 * Hh];
__device__ __nv_bfloat16 g_Wx_lo[(size_t)G4 * Hh];
__device__ float g_Wh[(size_t)G4 * Hh];          // recurrent half, fp32
__device__ float g_bias[G4];
__device__ float g_gx[(size_t)Tt * Bb * G4];     // x @ Wx^T + b
__device__ float g_h[2][Bb * Hh];
__device__ float g_c[Bb * Hh];

// ---------------------------------------------------------------------------
// PTX helpers — ONLY non-'a' instructions (mma.sync sm_80+, cp.async sm_80+)
// ---------------------------------------------------------------------------
__device__ __forceinline__ uint32_t smem_u32(const void* p) {
    uint32_t a;
    asm("{ .reg .u64 t; cvta.to.shared.u64 t, %1; cvt.u32.u64 %0, t; }" : "=r"(a) : "l"(p));
    return a;
}

__device__ __forceinline__ void cp16(uint32_t dst, const void* src) {
    asm volatile("cp.async.cg.shared.global [%0], [%1], 16;" :: "r"(dst), "l"(src) : "memory");
}
#define CP_COMMIT() asm volatile("cp.async.commit_group;" ::: "memory")
template <int N>
__device__ __forceinline__ void cp_wait() {
    asm volatile("cp.async.wait_group %0;" :: "n"(N) : "memory");
}

__device__ __forceinline__ void mma16816(float* c, const uint32_t* a, const uint32_t* b) {
    asm volatile(
        "mma.sync.aligned.m16n8k16.row.col.f32.bf16.bf16.f32 "
        "{%0,%1,%2,%3}, {%4,%5,%6,%7}, {%8,%9}, {%0,%1,%2,%3};"
        : "+f"(c[0]), "+f"(c[1]), "+f"(c[2]), "+f"(c[3])
        : "r"(a[0]), "r"(a[1]), "r"(a[2]), "r"(a[3]), "r"(b[0]), "r"(b[1]));
}

// ---------------------------------------------------------------------------
// Prep: split x into bf16 hi/lo
// ---------------------------------------------------------------------------
__global__ void split_x_kernel(const float* __restrict__ x) {
    size_t total = (size_t)Tt * Bb * Hh;
    size_t stride = (size_t)gridDim.x * blockDim.x;
    for (size_t i = (size_t)blockIdx.x * blockDim.x + threadIdx.x; i < total; i += stride) {
        float v = x[i];
        __nv_bfloat16 hi = __float2bfloat16(v);
        g_x_hi[i] = hi;
        g_x_lo[i] = __float2bfloat16(v - __bfloat162float(hi));
    }
}

// ---------------------------------------------------------------------------
// Repack weights (unit-major rows). Wx -> bf16 hi/lo; Wh -> fp32.
// ---------------------------------------------------------------------------
__global__ void repack_kernel(const float* __restrict__ Wi, const float* __restrict__ Wf,
                              const float* __restrict__ Wc, const float* __restrict__ Wo,
                              const float* __restrict__ bi, const float* __restrict__ bf,
                              const float* __restrict__ bc, const float* __restrict__ bo) {
    size_t total = (size_t)G4 * K2;
    size_t stride = (size_t)gridDim.x * blockDim.x;
    for (size_t idx = (size_t)blockIdx.x * blockDim.x + threadIdx.x; idx < total; idx += stride) {
        int j = (int)(idx / K2);
        int k = (int)(idx % K2);
        int u = j >> 2, g = j & 3;
        const float* src = (g == 0) ? Wi : (g == 1) ? Wf : (g == 2) ? Wc : Wo;
        float v = src[(size_t)u * K2 + k];
        if (k < Hh) {
            __nv_bfloat16 hi = __float2bfloat16(v);
            g_Wx_hi[(size_t)j * Hh + k] = hi;
            g_Wx_lo[(size_t)j * Hh + k] = __float2bfloat16(v - __bfloat162float(hi));
        } else {
            g_Wh[(size_t)j * Hh + (k - Hh)] = v;
        }
    }
    for (int j = blockIdx.x * blockDim.x + threadIdx.x; j < G4; j += (int)stride) {
        int u = j >> 2, g = j & 3;
        const float* sb = (g == 0) ? bi : (g == 1) ? bf : (g == 2) ? bc : bo;
        g_bias[j] = sb[u];
    }
}

__global__ void init_hc_kernel() {
    int i = blockIdx.x * blockDim.x + threadIdx.x;
    if (i < Bb * Hh) { g_h[0][i] = 0.0f; g_c[i] = 0.0f; }
}

// ---------------------------------------------------------------------------
// x-GEMM via mma.sync: gx[m][n] = sum_k x[m][k]*Wx[n][k] + bias[n]
// bf16 split: D += Ah*Bh + Ah*Bl + Al*Bh (fp32 accum).
// CTA tile 128x128, 8 warps (2x4), warp tile 64x32 = 4x4 m16n8k16.
// K chunks of 64, cp.async double-buffered. Smem rows stride 72 bf16 (144B)
// => conflict-free 32-bit fragment loads.
// ---------------------------------------------------------------------------
#define RS 72                          // row stride in bf16
#define ARR (128 * RS * 2)             // bytes per tile array
#define GX_SMEM (2 * 4 * ARR)          // 2 buffers x {Ah,Al,Bh,Bl} = 147456 B

__global__ __launch_bounds__(256) void gemm_x_mma() {
    extern __shared__ char smem[];
    const uint32_t sbase = smem_u32(smem);
    const int tid = threadIdx.x;
    const int w = tid >> 5;
    const int lane = tid & 31;
    const int g = lane >> 2;
    const int t = lane & 3;
    const int n0 = blockIdx.x * 128;
    const int m0 = blockIdx.y * 128;
    const int wm = (w >> 2) * 64;   // warp m offset in tile
    const int wn = (w & 3) * 32;    // warp n offset in tile

    const __nv_bfloat16* __restrict__ xh = g_x_hi;
    const __nv_bfloat16* __restrict__ xl = g_x_lo;
    const __nv_bfloat16* __restrict__ wh = g_Wx_hi;
    const __nv_bfloat16* __restrict__ wl = g_Wx_lo;

    // Stage one 64-wide K chunk into buffer b (4 arrays, 128 rows x 4 x 16B each)
    auto stage = [&](int ch, int b) {
        uint32_t base = sbase + b * 4 * ARR;
#pragma unroll
        for (int it = 0; it < 4; it++) {
            int idx = it * 256 + tid;      // 0..1023
            int r = idx >> 3;              // 0..127
            int s = idx & 7;               // 0..7 (16B segments)
            uint32_t doff = (uint32_t)(r * RS + s * 8) * 2;
            size_t asrc = (size_t)(m0 + r) * Hh + ch * 64 + s * 8;
            size_t bsrc = (size_t)(n0 + r) * Hh + ch * 64 + s * 8;
            cp16(base + 0 * ARR + doff, xh + asrc);
            cp16(base + 1 * ARR + doff, xl + asrc);
            cp16(base + 2 * ARR + doff, wh + bsrc);
            cp16(base + 3 * ARR + doff, wl + bsrc);
        }
        CP_COMMIT();
    };

    float C[4][4][4];
#pragma unroll
    for (int i = 0; i < 4; i++)
#pragma unroll
        for (int j = 0; j < 4; j++)
#pragma unroll
            for (int q = 0; q < 4; q++) C[i][j][q] = 0.0f;

    stage(0, 0);

    for (int ch = 0; ch < 16; ch++) {
        if (ch < 15) stage(ch + 1, (ch + 1) & 1);
        if (ch < 15) cp_wait<1>(); else cp_wait<0>();
        __syncthreads();

        const __nv_bfloat16* buf = reinterpret_cast<const __nv_bfloat16*>(smem + (ch & 1) * 4 * ARR);
        const __nv_bfloat16* Ah = buf;
        const __nv_bfloat16* Al = buf + 128 * RS;
        const __nv_bfloat16* Bh = buf + 2 * 128 * RS;
        const __nv_bfloat16* Bl = buf + 3 * 128 * RS;

#pragma unroll
        for (int kk = 0; kk < 64; kk += 16) {
            uint32_t ah[4][4], al[4][4], bh[4][2], bl[4][2];
#pragma unroll
            for (int mt = 0; mt < 4; mt++) {
                int R = wm + mt * 16;
                ah[mt][0] = *(const uint32_t*)&Ah[(R + g) * RS + kk + 2 * t];
                ah[mt][1] = *(const uint32_t*)&Ah[(R + g + 8) * RS + kk + 2 * t];
                ah[mt][2] = *(const uint32_t*)&Ah[(R + g) * RS + kk + 2 * t + 8];
                ah[mt][3] = *(const uint32_t*)&Ah[(R + g + 8) * RS + kk + 2 * t + 8];
                al[mt][0] = *(const uint32_t*)&Al[(R + g) * RS + kk + 2 * t];
                al[mt][1] = *(const uint32_t*)&Al[(R + g + 8) * RS + kk + 2 * t];
                al[mt][2] = *(const uint32_t*)&Al[(R + g) * RS + kk + 2 * t + 8];
                al[mt][3] = *(const uint32_t*)&Al[(R + g + 8) * RS + kk + 2 * t + 8];
            }
#pragma unroll
            for (int nt = 0; nt < 4; nt++) {
                int S = wn + nt * 8;
                bh[nt][0] = *(const uint32_t*)&Bh[(S + g) * RS + kk + 2 * t];
                bh[nt][1] = *(const uint32_t*)&Bh[(S + g) * RS + kk + 2 * t + 8];
                bl[nt][0] = *(const uint32_t*)&Bl[(S + g) * RS + kk + 2 * t];
                bl[nt][1] = *(const uint32_t*)&Bl[(S + g) * RS + kk + 2 * t + 8];
            }
#pragma unroll
            for (int mt = 0; mt < 4; mt++)
#pragma unroll
                for (int nt = 0; nt < 4; nt++) {
                    mma16816(C[mt][nt], ah[mt], bh[nt]);
                    mma16816(C[mt][nt], ah[mt], bl[nt]);
                    mma16816(C[mt][nt], al[mt], bh[nt]);
                }
        }
        __syncthreads();
    }

    // Epilogue: add bias, store fp32
#pragma unroll
    for (int mt = 0; mt < 4; mt++) {
        int row = m0 + wm + mt * 16 + g;
#pragma unroll
        for (int nt = 0; nt < 4; nt++) {
            int col = n0 + wn + nt * 8 + 2 * t;
            float2 bv = *reinterpret_cast<const float2*>(g_bias + col);
            float2 o0 = { C[mt][nt][0] + bv.x, C[mt][nt][1] + bv.y };
            float2 o1 = { C[mt][nt][2] + bv.x, C[mt][nt][3] + bv.y };
            *reinterpret_cast<float2*>(g_gx + (size_t)row * G4 + col) = o0;
            *reinterpret_cast<float2*>(g_gx + (size_t)(row + 8) * G4 + col) = o1;
        }
    }
}

// ---------------------------------------------------------------------------
// Recurrent step (fp32, 256 threads, Wh in SMEM).
// Block bu owns units [bu*8, bu*8+8) = unit-major rows [bu*32, bu*32+32).
// Thread (m2 = tid>>3, n4 = tid&7): 2 batch rows x 4 gates of unit bu*8+n4.
// ---------------------------------------------------------------------------
#define WS_FLOATS (Hh * 32)
#define HS_STRIDE 66
#define HS_FLOATS (64 * HS_STRIDE)
#define STEP_SMEM ((WS_FLOATS + 2 * HS_FLOATS) * 4)

__device__ __forceinline__ float sigf(float v) { return 1.0f / (1.0f + __expf(-v)); }
__device__ __forceinline__ float tanhf_fast(float v) {
    float e = __expf(-2.0f * fabsf(v));
    float r = (1.0f - e) / (1.0f + e);
    return (v >= 0.0f) ? r : -r;
}

__global__ __launch_bounds__(256) void lstm_step_kernel(int t, float* __restrict__ out_seq) {
    extern __shared__ float sm[];
    float* ws = sm;                    // [1024][32]  ws[k][n] = Wh[bu*32+n][k]
    float* hs = sm + WS_FLOATS;        // [2][64][HS_STRIDE]
    const int tid = threadIdx.x;
    const int bu = blockIdx.x;
    const int n4 = tid & 7;
    const int m2 = tid >> 3;
    const float* __restrict__ h_in = g_h[t & 1];
    float* __restrict__ h_out = g_h[(t + 1) & 1];

    {
        const float* wsrc = g_Wh + (size_t)bu * 32 * Hh;
#pragma unroll
        for (int it = 0; it < 32; it++) {
            int idx = it * 256 + tid;
            int n = idx & 31;
            int kq = (idx >> 5) << 2;
            float4 wv = *reinterpret_cast<const float4*>(wsrc + (size_t)n * Hh + kq);
            ws[(kq + 0) * 32 + n] = wv.x;
            ws[(kq + 1) * 32 + n] = wv.y;
            ws[(kq + 2) * 32 + n] = wv.z;
            ws[(kq + 3) * 32 + n] = wv.w;
        }
    }

    float acc[2][4];
#pragma unroll
    for (int i = 0; i < 2; i++)
#pragma unroll
        for (int j = 0; j < 4; j++) acc[i][j] = 0.0f;

    const int lm = tid & 63;
    const int lq = tid >> 6;  // 0..3
    float4 v[4];
#pragma unroll
    for (int j = 0; j < 4; j++)
        v[j] = *reinterpret_cast<const float4*>(h_in + (size_t)lm * Hh + (lq * 4 + j) * 4);

    for (int ch = 0; ch < 16; ch++) {
        float* hb = hs + (ch & 1) * HS_FLOATS;
#pragma unroll
        for (int j = 0; j < 4; j++) {
            int kk = (lq * 4 + j) * 4;
            hb[(kk + 0) * HS_STRIDE + lm] = v[j].x;
            hb[(kk + 1) * HS_STRIDE + lm] = v[j].y;
            hb[(kk + 2) * HS_STRIDE + lm] = v[j].z;
            hb[(kk + 3) * HS_STRIDE + lm] = v[j].w;
        }
        __syncthreads();
        if (ch < 15) {
            int k0n = (ch + 1) * 64;
#pragma unroll
            for (int j = 0; j < 4; j++)
                v[j] = *reinterpret_cast<const float4*>(h_in + (size_t)lm * Hh + k0n + (lq * 4 + j) * 4);
        }
        const float* wk = ws + ch * 64 * 32;
#pragma unroll 16
        for (int kk = 0; kk < 64; kk++) {
            float2 a2 = *reinterpret_cast<const float2*>(hb + kk * HS_STRIDE + m2 * 2);
            float4 b4 = *reinterpret_cast<const float4*>(wk + kk * 32 + n4 * 4);
            acc[0][0] = fmaf(a2.x, b4.x, acc[0][0]);
            acc[0][1] = fmaf(a2.x, b4.y, acc[0][1]);
            acc[0][2] = fmaf(a2.x, b4.z, acc[0][2]);
            acc[0][3] = fmaf(a2.x, b4.w, acc[0][3]);
            acc[1][0] = fmaf(a2.y, b4.x, acc[1][0]);
            acc[1][1] = fmaf(a2.y, b4.y, acc[1][1]);
            acc[1][2] = fmaf(a2.y, b4.z, acc[1][2]);
            acc[1][3] = fmaf(a2.y, b4.w, acc[1][3]);
        }
    }

    const int u = bu * 8 + n4;
#pragma unroll
    for (int i = 0; i < 2; i++) {
        int m = m2 * 2 + i;
        float4 gx4 = *reinterpret_cast<const float4*>(
            g_gx + ((size_t)t * Bb + m) * G4 + (size_t)(bu * 32 + n4 * 4));
        float it = sigf(gx4.x + acc[i][0]);
        float ft = sigf(gx4.y + acc[i][1]);
        float gt = tanhf_fast(gx4.z + acc[i][2]);
        float ot = sigf(gx4.w + acc[i][3]);
        int hc = m * Hh + u;
        float cn = fmaf(ft, g_c[hc], it * gt);
        g_c[hc] = cn;
        float hn = ot * tanhf_fast(cn);
        h_out[hc] = hn;
        out_seq[(size_t)t * (Bb * Hh) + hc] = hn;
    }
}

__global__ void finalize_kernel(float* __restrict__ out) {
    int i = blockIdx.x * blockDim.x + threadIdx.x;
    if (i < Bb * Hh) {
        size_t base = (size_t)Tt * Bb * Hh;
        out[base + i] = g_h[Tt & 1][i];
        out[base + Bb * Hh + i] = g_c[i];
    }
}

// ---------------------------------------------------------------------------
extern "C" void kernel_launch(void* const* d_in, const int* in_sizes, int n_in,
                              void* d_out, int out_size) {
    const float* x  = (const float*)d_in[0];
    const float* Wi = (const float*)d_in[1];
    const float* bi = (const float*)d_in[2];
    const float* Wf = (const float*)d_in[3];
    const float* bf = (const float*)d_in[4];
    const float* Wc = (const float*)d_in[5];
    const float* bc = (const float*)d_in[6];
    const float* Wo = (const float*)d_in[7];
    const float* bo = (const float*)d_in[8];
    float* out = (float*)d_out;

    cudaFuncSetAttribute(gemm_x_mma, cudaFuncAttributeMaxDynamicSharedMemorySize, GX_SMEM);
    cudaFuncSetAttribute(lstm_step_kernel, cudaFuncAttributeMaxDynamicSharedMemorySize, STEP_SMEM);

    repack_kernel<<<512, 256>>>(Wi, Wf, Wc, Wo, bi, bf, bc, bo);
    split_x_kernel<<<1024, 256>>>(x);
    init_hc_kernel<<<(Bb * Hh + 255) / 256, 256>>>();

    // x-GEMM on tensor cores (mma.sync): [32768 x 4096 x 1024], bf16 hi/lo split
    gemm_x_mma<<<dim3(G4 / 128, (Tt * Bb) / 128), 256, GX_SMEM>>>();

    for (int t = 0; t < Tt; t++) {
        lstm_step_kernel<<<128, 256, STEP_SMEM>>>(t, out);
    }

    finalize_kernel<<<(Bb * Hh + 255) / 256, 256>>>(out);
}

// round 5
// speedup vs baseline: 2.3406x; 1.7319x over previous
#include <cuda_runtime.h>
#include <cuda_bf16.h>
#include <cstdint>
#include <math.h>

#define Tt 512
#define Bb 64
#define Hh 1024
#define G4 4096
#define K2 2048
#define NBLK 128

// ---------------------------------------------------------------------------
// Device globals. Weight rows UNIT-MAJOR: j = u*4 + g, g in {i,f,c,o}.
// ---------------------------------------------------------------------------
__device__ __nv_bfloat16 g_x_hi[(size_t)Tt * Bb * Hh];
__device__ __nv_bfloat16 g_x_lo[(size_t)Tt * Bb * Hh];
__device__ __nv_bfloat16 g_Wx_hi[(size_t)G4 * Hh];
__device__ __nv_bfloat16 g_Wx_lo[(size_t)G4 * Hh];
__device__ __nv_bfloat16 g_Wh_hi[(size_t)G4 * Hh];
__device__ __nv_bfloat16 g_Wh_lo[(size_t)G4 * Hh];
__device__ float g_bias[G4];
__device__ float g_gx[(size_t)Tt * Bb * G4];
__device__ __nv_bfloat16 g_hb_hi[2][Bb * Hh];
__device__ __nv_bfloat16 g_hb_lo[2][Bb * Hh];
__device__ volatile int g_flags[NBLK * 32];
__device__ volatile int g_release;

// ---------------------------------------------------------------------------
// PTX helpers — non-'a' instructions only (sm_80 baseline + ldmatrix sm_75)
// ---------------------------------------------------------------------------
__device__ __forceinline__ uint32_t smem_u32(const void* p) {
    uint32_t a;
    asm("{ .reg .u64 t; cvta.to.shared.u64 t, %1; cvt.u32.u64 %0, t; }" : "=r"(a) : "l"(p));
    return a;
}
__device__ __forceinline__ void cp16(uint32_t dst, const void* src) {
    asm volatile("cp.async.cg.shared.global [%0], [%1], 16;" :: "r"(dst), "l"(src) : "memory");
}
#define CP_COMMIT() asm volatile("cp.async.commit_group;" ::: "memory")
template <int N>
__device__ __forceinline__ void cp_wait() {
    asm volatile("cp.async.wait_group %0;" :: "n"(N) : "memory");
}
__device__ __forceinline__ void mma16816(float* c, const uint32_t* a, const uint32_t* b) {
    asm volatile(
        "mma.sync.aligned.m16n8k16.row.col.f32.bf16.bf16.f32 "
        "{%0,%1,%2,%3}, {%4,%5,%6,%7}, {%8,%9}, {%0,%1,%2,%3};"
        : "+f"(c[0]), "+f"(c[1]), "+f"(c[2]), "+f"(c[3])
        : "r"(a[0]), "r"(a[1]), "r"(a[2]), "r"(a[3]), "r"(b[0]), "r"(b[1]));
}
__device__ __forceinline__ void ldsm_x4(uint32_t* r, uint32_t addr) {
    asm volatile("ldmatrix.sync.aligned.m8n8.x4.shared.b16 {%0,%1,%2,%3}, [%4];"
                 : "=r"(r[0]), "=r"(r[1]), "=r"(r[2]), "=r"(r[3]) : "r"(addr));
}
__device__ __forceinline__ void ldsm_x2(uint32_t* r, uint32_t addr) {
    asm volatile("ldmatrix.sync.aligned.m8n8.x2.shared.b16 {%0,%1}, [%2];"
                 : "=r"(r[0]), "=r"(r[1]) : "r"(addr));
}
__device__ __forceinline__ void nsleep() { asm volatile("nanosleep.u32 40;"); }

__device__ __forceinline__ float sigf(float v) { return 1.0f / (1.0f + __expf(-v)); }
__device__ __forceinline__ float tanhf_fast(float v) {
    float e = __expf(-2.0f * fabsf(v));
    float r = (1.0f - e) / (1.0f + e);
    return (v >= 0.0f) ? r : -r;
}

// ---------------------------------------------------------------------------
// Prep kernels
// ---------------------------------------------------------------------------
__global__ void split_x_kernel(const float* __restrict__ x) {
    size_t total = (size_t)Tt * Bb * Hh;
    size_t stride = (size_t)gridDim.x * blockDim.x;
    for (size_t i = (size_t)blockIdx.x * blockDim.x + threadIdx.x; i < total; i += stride) {
        float v = x[i];
        __nv_bfloat16 hi = __float2bfloat16(v);
        g_x_hi[i] = hi;
        g_x_lo[i] = __float2bfloat16(v - __bfloat162float(hi));
    }
}

__global__ void repack_kernel(const float* __restrict__ Wi, const float* __restrict__ Wf,
                              const float* __restrict__ Wc, const float* __restrict__ Wo,
                              const float* __restrict__ bi, const float* __restrict__ bf,
                              const float* __restrict__ bc, const float* __restrict__ bo) {
    size_t total = (size_t)G4 * K2;
    size_t stride = (size_t)gridDim.x * blockDim.x;
    for (size_t idx = (size_t)blockIdx.x * blockDim.x + threadIdx.x; idx < total; idx += stride) {
        int j = (int)(idx / K2);
        int k = (int)(idx % K2);
        int u = j >> 2, g = j & 3;
        const float* src = (g == 0) ? Wi : (g == 1) ? Wf : (g == 2) ? Wc : Wo;
        float v = src[(size_t)u * K2 + k];
        __nv_bfloat16 hi = __float2bfloat16(v);
        __nv_bfloat16 lo = __float2bfloat16(v - __bfloat162float(hi));
        if (k < Hh) {
            g_Wx_hi[(size_t)j * Hh + k] = hi;
            g_Wx_lo[(size_t)j * Hh + k] = lo;
        } else {
            g_Wh_hi[(size_t)j * Hh + (k - Hh)] = hi;
            g_Wh_lo[(size_t)j * Hh + (k - Hh)] = lo;
        }
    }
    for (int j = blockIdx.x * blockDim.x + threadIdx.x; j < G4; j += (int)stride) {
        int u = j >> 2, g = j & 3;
        const float* sb = (g == 0) ? bi : (g == 1) ? bf : (g == 2) ? bc : bo;
        g_bias[j] = sb[u];
    }
}

__global__ void init_state_kernel() {
    int i = blockIdx.x * blockDim.x + threadIdx.x;
    int stride = gridDim.x * blockDim.x;
    __nv_bfloat16 z = __float2bfloat16(0.0f);
    for (int k = i; k < 2 * Bb * Hh; k += stride) {
        g_hb_hi[0][k % (Bb * Hh)] = z;  // covers both parities via the 2x range
        g_hb_hi[k / (Bb * Hh)][k % (Bb * Hh)] = z;
        g_hb_lo[k / (Bb * Hh)][k % (Bb * Hh)] = z;
    }
    for (int k = i; k < NBLK * 32; k += stride) g_flags[k] = 0;
    if (i == 0) g_release = 0;
}

// ---------------------------------------------------------------------------
// x-GEMM via mma.sync (proven R4): gx = x @ Wx^T + b, bf16 hi/lo 3-product.
// ---------------------------------------------------------------------------
#define RS 72
#define ARR (128 * RS * 2)
#define GX_SMEM (2 * 4 * ARR)

__global__ __launch_bounds__(256) void gemm_x_mma() {
    extern __shared__ char smem[];
    const uint32_t sbase = smem_u32(smem);
    const int tid = threadIdx.x;
    const int w = tid >> 5;
    const int lane = tid & 31;
    const int g = lane >> 2;
    const int t = lane & 3;
    const int n0 = blockIdx.x * 128;
    const int m0 = blockIdx.y * 128;
    const int wm = (w >> 2) * 64;
    const int wn = (w & 3) * 32;

    const __nv_bfloat16* __restrict__ xh = g_x_hi;
    const __nv_bfloat16* __restrict__ xl = g_x_lo;
    const __nv_bfloat16* __restrict__ wh = g_Wx_hi;
    const __nv_bfloat16* __restrict__ wl = g_Wx_lo;

    auto stage = [&](int ch, int b) {
        uint32_t base = sbase + b * 4 * ARR;
#pragma unroll
        for (int it = 0; it < 4; it++) {
            int idx = it * 256 + tid;
            int r = idx >> 3;
            int s = idx & 7;
            uint32_t doff = (uint32_t)(r * RS + s * 8) * 2;
            size_t asrc = (size_t)(m0 + r) * Hh + ch * 64 + s * 8;
            size_t bsrc = (size_t)(n0 + r) * Hh + ch * 64 + s * 8;
            cp16(base + 0 * ARR + doff, xh + asrc);
            cp16(base + 1 * ARR + doff, xl + asrc);
            cp16(base + 2 * ARR + doff, wh + bsrc);
            cp16(base + 3 * ARR + doff, wl + bsrc);
        }
        CP_COMMIT();
    };

    float C[4][4][4];
#pragma unroll
    for (int i = 0; i < 4; i++)
#pragma unroll
        for (int j = 0; j < 4; j++)
#pragma unroll
            for (int q = 0; q < 4; q++) C[i][j][q] = 0.0f;

    stage(0, 0);
    for (int ch = 0; ch < 16; ch++) {
        if (ch < 15) stage(ch + 1, (ch + 1) & 1);
        if (ch < 15) cp_wait<1>(); else cp_wait<0>();
        __syncthreads();
        const __nv_bfloat16* buf = reinterpret_cast<const __nv_bfloat16*>(smem + (ch & 1) * 4 * ARR);
        const __nv_bfloat16* Ah = buf;
        const __nv_bfloat16* Al = buf + 128 * RS;
        const __nv_bfloat16* Bh = buf + 2 * 128 * RS;
        const __nv_bfloat16* Bl = buf + 3 * 128 * RS;
#pragma unroll
        for (int kk = 0; kk < 64; kk += 16) {
            uint32_t ah[4][4], al[4][4], bh[4][2], bl[4][2];
#pragma unroll
            for (int mt = 0; mt < 4; mt++) {
                int R = wm + mt * 16;
                ah[mt][0] = *(const uint32_t*)&Ah[(R + g) * RS + kk + 2 * t];
                ah[mt][1] = *(const uint32_t*)&Ah[(R + g + 8) * RS + kk + 2 * t];
                ah[mt][2] = *(const uint32_t*)&Ah[(R + g) * RS + kk + 2 * t + 8];
                ah[mt][3] = *(const uint32_t*)&Ah[(R + g + 8) * RS + kk + 2 * t + 8];
                al[mt][0] = *(const uint32_t*)&Al[(R + g) * RS + kk + 2 * t];
                al[mt][1] = *(const uint32_t*)&Al[(R + g + 8) * RS + kk + 2 * t];
                al[mt][2] = *(const uint32_t*)&Al[(R + g) * RS + kk + 2 * t + 8];
                al[mt][3] = *(const uint32_t*)&Al[(R + g + 8) * RS + kk + 2 * t + 8];
            }
#pragma unroll
            for (int nt = 0; nt < 4; nt++) {
                int S = wn + nt * 8;
                bh[nt][0] = *(const uint32_t*)&Bh[(S + g) * RS + kk + 2 * t];
                bh[nt][1] = *(const uint32_t*)&Bh[(S + g) * RS + kk + 2 * t + 8];
                bl[nt][0] = *(const uint32_t*)&Bl[(S + g) * RS + kk + 2 * t];
                bl[nt][1] = *(const uint32_t*)&Bl[(S + g) * RS + kk + 2 * t + 8];
            }
#pragma unroll
            for (int mt = 0; mt < 4; mt++)
#pragma unroll
                for (int nt = 0; nt < 4; nt++) {
                    mma16816(C[mt][nt], ah[mt], bh[nt]);
                    mma16816(C[mt][nt], ah[mt], bl[nt]);
                    mma16816(C[mt][nt], al[mt], bh[nt]);
                }
        }
        __syncthreads();
    }
#pragma unroll
    for (int mt = 0; mt < 4; mt++) {
        int row = m0 + wm + mt * 16 + g;
#pragma unroll
        for (int nt = 0; nt < 4; nt++) {
            int col = n0 + wn + nt * 8 + 2 * t;
            float2 bv = *reinterpret_cast<const float2*>(g_bias + col);
            float2 o0 = { C[mt][nt][0] + bv.x, C[mt][nt][1] + bv.y };
            float2 o1 = { C[mt][nt][2] + bv.x, C[mt][nt][3] + bv.y };
            *reinterpret_cast<float2*>(g_gx + (size_t)row * G4 + col) = o0;
            *reinterpret_cast<float2*>(g_gx + (size_t)(row + 8) * G4 + col) = o1;
        }
    }
}

// ---------------------------------------------------------------------------
// Persistent recurrent kernel: 128 blocks x 256 threads, all 512 steps.
// SMEM layout (bytes):
//   WH hi: [32][1032] bf16 @ 0        (66048)
//   WH lo:                  @ 66048   (66048)
//   H buffers: 2 x { hi [64][136], lo [64][136] } bf16 @ 132096 (2x34816)
//   GXS: [64][36] float @ 201728      (9216)   total 210944
// ---------------------------------------------------------------------------
#define WH_HI_OFF 0
#define WH_LO_OFF 66048
#define HB_OFF    132096
#define HBUF_SZ   34816
#define HLO_SUB   17408
#define GXS_OFF   201728
#define PERSIST_SMEM 210944

__global__ __launch_bounds__(256, 1) void lstm_persist(float* __restrict__ out) {
    extern __shared__ char smem[];
    const uint32_t sbase = smem_u32(smem);
    const int tid = threadIdx.x;
    const int bu = blockIdx.x;
    const int w = tid >> 5;
    const int lane = tid & 31;
    const int g = lane >> 2;
    const int tq = lane & 3;
    const int wm = (w >> 2) * 32;   // 0 or 32
    const int wn = (w & 3) * 8;     // 0,8,16,24

    // ---- load Wh slice (rows bu*32 .. +32) into smem, bf16 hi/lo ----
    {
        const __nv_bfloat16* shi = g_Wh_hi + (size_t)bu * 32 * Hh;
        const __nv_bfloat16* slo = g_Wh_lo + (size_t)bu * 32 * Hh;
#pragma unroll
        for (int q = 0; q < 16; q++) {
            int idx = q * 256 + tid;          // 0..4095
            int row = idx >> 7;               // 0..31
            int seg = idx & 127;              // 16B segments
            uint32_t doff = (uint32_t)(row * 1032 + seg * 8) * 2;
            cp16(sbase + WH_HI_OFF + doff, shi + (size_t)row * Hh + seg * 8);
            cp16(sbase + WH_LO_OFF + doff, slo + (size_t)row * Hh + seg * 8);
        }
        CP_COMMIT();
        cp_wait<0>();
    }
    __syncthreads();

    // ldmatrix lane addressing
    const int lrow = (lane & 7) + ((lane >> 3) & 1) * 8;   // 0..15
    const int lcol = (lane >> 4) * 8;                      // 0 or 8
    const uint32_t a_lane_off = (uint32_t)((wm + lrow) * 136 + lcol) * 2;
    const uint32_t b_lane_off = (uint32_t)((wn + (lane & 7)) * 1032 + ((lane >> 3) & 1) * 8) * 2;
    const uint32_t b_hi_base = sbase + WH_HI_OFF + b_lane_off;
    const uint32_t b_lo_base = sbase + WH_LO_OFF + b_lane_off;

    // epilogue cell mapping (constant across steps)
    const int myMt = tq & 1;
    const int row0 = wm + myMt * 16 + g;
    const int row1 = row0 + 8;
    const int u_glob = bu * 8 + (wn >> 2) + (tq >> 1);

    float creg0 = 0.0f, creg1 = 0.0f;
    float hlast0 = 0.0f, hlast1 = 0.0f;
    const float* gxs = reinterpret_cast<const float*>(smem + GXS_OFF);

    for (int t = 0; t < Tt; t++) {
        const int par = t & 1;
        const __nv_bfloat16* hsrc_hi = g_hb_hi[par];
        const __nv_bfloat16* hsrc_lo = g_hb_lo[par];

        // gx prefetch for this step: 64 rows x 32 cols fp32
        {
#pragma unroll
            for (int q = 0; q < 2; q++) {
                int idx = q * 256 + tid;      // 0..511
                int row = idx >> 3;           // 0..63
                int seg = idx & 7;            // 4-float segments
                cp16(sbase + GXS_OFF + (uint32_t)(row * 144 + seg * 16),
                     g_gx + ((size_t)t * Bb + row) * G4 + bu * 32 + seg * 4);
            }
            CP_COMMIT();
        }

        // stage h chunk 0
        auto stage_h = [&](int ch) {
            uint32_t base = sbase + HB_OFF + (uint32_t)(ch & 1) * HBUF_SZ;
#pragma unroll
            for (int q = 0; q < 8; q++) {
                int sel = q >> 2;                 // 0=hi, 1=lo
                int idx = (q & 3) * 256 + tid;    // 0..1023
                int row = idx >> 4;               // 0..63
                int seg = idx & 15;               // 16B segs (8 bf16)
                uint32_t doff = (uint32_t)(row * 136 + seg * 8) * 2 + (uint32_t)sel * HLO_SUB;
                const __nv_bfloat16* src = sel ? hsrc_lo : hsrc_hi;
                cp16(base + doff, src + (size_t)row * Hh + ch * 128 + seg * 8);
            }
            CP_COMMIT();
        };
        stage_h(0);

        float C[2][4];
#pragma unroll
        for (int q = 0; q < 4; q++) { C[0][q] = 0.0f; C[1][q] = 0.0f; }

        for (int ch = 0; ch < 8; ch++) {
            if (ch < 7) { stage_h(ch + 1); cp_wait<1>(); }
            else cp_wait<0>();
            __syncthreads();
            const uint32_t abuf = sbase + HB_OFF + (uint32_t)(ch & 1) * HBUF_SZ + a_lane_off;
#pragma unroll
            for (int k8 = 0; k8 < 8; k8++) {
                const uint32_t kb = (uint32_t)k8 * 32;
                uint32_t bh[2], bl[2], ah[4], al[4];
                ldsm_x2(bh, b_hi_base + (uint32_t)ch * 256 + kb);
                ldsm_x2(bl, b_lo_base + (uint32_t)ch * 256 + kb);
                // mt = 0
                ldsm_x4(ah, abuf + kb);
                ldsm_x4(al, abuf + HLO_SUB + kb);
                mma16816(C[0], ah, bh);
                mma16816(C[0], ah, bl);
                mma16816(C[0], al, bh);
                // mt = 1 (+16 rows = +16*136*2 bytes)
                ldsm_x4(ah, abuf + 4352 + kb);
                ldsm_x4(al, abuf + HLO_SUB + 4352 + kb);
                mma16816(C[1], ah, bh);
                mma16816(C[1], ah, bl);
                mma16816(C[1], al, bh);
            }
            __syncthreads();
        }

        // ---- epilogue ----
        float v[2][4], p[2][4];
#pragma unroll
        for (int mt = 0; mt < 2; mt++) {
            int r0 = wm + mt * 16 + g;
            int r1 = r0 + 8;
            int col = wn + 2 * tq;
            v[mt][0] = C[mt][0] + gxs[r0 * 36 + col];
            v[mt][1] = C[mt][1] + gxs[r0 * 36 + col + 1];
            v[mt][2] = C[mt][2] + gxs[r1 * 36 + col];
            v[mt][3] = C[mt][3] + gxs[r1 * 36 + col + 1];
        }
#pragma unroll
        for (int mt = 0; mt < 2; mt++)
#pragma unroll
            for (int q = 0; q < 4; q++)
                p[mt][q] = __shfl_xor_sync(0xffffffffu, v[mt][q], 1);

        float ii0, ff0, cc0, oo0, ii1, ff1, cc1, oo1;
        if (myMt == 0) {
            ii0 = v[0][0]; ff0 = v[0][1]; cc0 = p[0][0]; oo0 = p[0][1];
            ii1 = v[0][2]; ff1 = v[0][3]; cc1 = p[0][2]; oo1 = p[0][3];
        } else {
            ii0 = p[1][0]; ff0 = p[1][1]; cc0 = v[1][0]; oo0 = v[1][1];
            ii1 = p[1][2]; ff1 = p[1][3]; cc1 = v[1][2]; oo1 = v[1][3];
        }

        float cn0 = fmaf(sigf(ff0), creg0, sigf(ii0) * tanhf_fast(cc0));
        float cn1 = fmaf(sigf(ff1), creg1, sigf(ii1) * tanhf_fast(cc1));
        creg0 = cn0; creg1 = cn1;
        float hn0 = sigf(oo0) * tanhf_fast(cn0);
        float hn1 = sigf(oo1) * tanhf_fast(cn1);
        hlast0 = hn0; hlast1 = hn1;

        out[(size_t)t * (Bb * Hh) + row0 * Hh + u_glob] = hn0;
        out[(size_t)t * (Bb * Hh) + row1 * Hh + u_glob] = hn1;

        const int np = (t + 1) & 1;
        __nv_bfloat16 h0h = __float2bfloat16(hn0);
        __nv_bfloat16 h1h = __float2bfloat16(hn1);
        g_hb_hi[np][row0 * Hh + u_glob] = h0h;
        g_hb_hi[np][row1 * Hh + u_glob] = h1h;
        g_hb_lo[np][row0 * Hh + u_glob] = __float2bfloat16(hn0 - __bfloat162float(h0h));
        g_hb_lo[np][row1 * Hh + u_glob] = __float2bfloat16(hn1 - __bfloat162float(h1h));

        // ---- grid barrier ----
        __syncthreads();
        __threadfence();
        if (tid == 0) g_flags[bu * 32] = t + 1;
        if (bu == 0) {
            if (tid < NBLK) {
                while (g_flags[tid * 32] < t + 1) nsleep();
            }
            __syncthreads();
            if (tid == 0) { __threadfence(); g_release = t + 1; }
        } else {
            if (tid == 0) {
                while (g_release < t + 1) nsleep();
            }
        }
        __syncthreads();
        __threadfence();
    }

    // final h_T, c_T
    size_t base = (size_t)Tt * Bb * Hh;
    out[base + row0 * Hh + u_glob] = hlast0;
    out[base + row1 * Hh + u_glob] = hlast1;
    out[base + Bb * Hh + row0 * Hh + u_glob] = creg0;
    out[base + Bb * Hh + row1 * Hh + u_glob] = creg1;
}

// ---------------------------------------------------------------------------
extern "C" void kernel_launch(void* const* d_in, const int* in_sizes, int n_in,
                              void* d_out, int out_size) {
    const float* x  = (const float*)d_in[0];
    const float* Wi = (const float*)d_in[1];
    const float* bi = (const float*)d_in[2];
    const float* Wf = (const float*)d_in[3];
    const float* bf = (const float*)d_in[4];
    const float* Wc = (const float*)d_in[5];
    const float* bc = (const float*)d_in[6];
    const float* Wo = (const float*)d_in[7];
    const float* bo = (const float*)d_in[8];
    float* out = (float*)d_out;

    cudaFuncSetAttribute(gemm_x_mma, cudaFuncAttributeMaxDynamicSharedMemorySize, GX_SMEM);
    cudaFuncSetAttribute(lstm_persist, cudaFuncAttributeMaxDynamicSharedMemorySize, PERSIST_SMEM);

    repack_kernel<<<512, 256>>>(Wi, Wf, Wc, Wo, bi, bf, bc, bo);
    split_x_kernel<<<1024, 256>>>(x);
    init_state_kernel<<<512, 256>>>();

    gemm_x_mma<<<dim3(G4 / 128, (Tt * Bb) / 128), 256, GX_SMEM>>>();

    lstm_persist<<<NBLK, 256, PERSIST_SMEM>>>(out);
}

// round 6
// speedup vs baseline: 3.6536x; 1.5610x over previous
#include <cuda_runtime.h>
#include <cuda_bf16.h>
#include <cstdint>
#include <math.h>

#define Tt 512
#define Bb 64
#define Hh 1024
#define G4 4096
#define K2 2048
#define NBLK 128

// ---------------------------------------------------------------------------
// Device globals. Weight rows UNIT-MAJOR: j = u*4 + g, g in {i,f,c,o}.
// ---------------------------------------------------------------------------
__device__ __nv_bfloat16 g_x_hi[(size_t)Tt * Bb * Hh];
__device__ __nv_bfloat16 g_x_lo[(size_t)Tt * Bb * Hh];
__device__ __nv_bfloat16 g_Wx_hi[(size_t)G4 * Hh];
__device__ __nv_bfloat16 g_Wx_lo[(size_t)G4 * Hh];
__device__ __nv_bfloat16 g_Wh_hi[(size_t)G4 * Hh];
__device__ __nv_bfloat16 g_Wh_lo[(size_t)G4 * Hh];
__device__ float g_bias[G4];
__device__ float g_gx[(size_t)Tt * Bb * G4];
__device__ __nv_bfloat16 g_hb_hi[2][Bb * Hh];
__device__ __nv_bfloat16 g_hb_lo[2][Bb * Hh];
__device__ unsigned int g_ctr;

// ---------------------------------------------------------------------------
// PTX helpers — non-'a' instructions only
// ---------------------------------------------------------------------------
__device__ __forceinline__ uint32_t smem_u32(const void* p) {
    uint32_t a;
    asm("{ .reg .u64 t; cvta.to.shared.u64 t, %1; cvt.u32.u64 %0, t; }" : "=r"(a) : "l"(p));
    return a;
}
__device__ __forceinline__ void cp16(uint32_t dst, const void* src) {
    asm volatile("cp.async.cg.shared.global [%0], [%1], 16;" :: "r"(dst), "l"(src) : "memory");
}
#define CP_COMMIT() asm volatile("cp.async.commit_group;" ::: "memory")
template <int N>
__device__ __forceinline__ void cp_wait() {
    asm volatile("cp.async.wait_group %0;" :: "n"(N) : "memory");
}
__device__ __forceinline__ void mma16816(float* c, const uint32_t* a, const uint32_t* b) {
    asm volatile(
        "mma.sync.aligned.m16n8k16.row.col.f32.bf16.bf16.f32 "
        "{%0,%1,%2,%3}, {%4,%5,%6,%7}, {%8,%9}, {%0,%1,%2,%3};"
        : "+f"(c[0]), "+f"(c[1]), "+f"(c[2]), "+f"(c[3])
        : "r"(a[0]), "r"(a[1]), "r"(a[2]), "r"(a[3]), "r"(b[0]), "r"(b[1]));
}
__device__ __forceinline__ void mma16816b(float* c, const uint32_t* a, uint32_t b0, uint32_t b1) {
    asm volatile(
        "mma.sync.aligned.m16n8k16.row.col.f32.bf16.bf16.f32 "
        "{%0,%1,%2,%3}, {%4,%5,%6,%7}, {%8,%9}, {%0,%1,%2,%3};"
        : "+f"(c[0]), "+f"(c[1]), "+f"(c[2]), "+f"(c[3])
        : "r"(a[0]), "r"(a[1]), "r"(a[2]), "r"(a[3]), "r"(b0), "r"(b1));
}
__device__ __forceinline__ void ldsm_x4(uint32_t* r, uint32_t addr) {
    asm volatile("ldmatrix.sync.aligned.m8n8.x4.shared.b16 {%0,%1,%2,%3}, [%4];"
                 : "=r"(r[0]), "=r"(r[1]), "=r"(r[2]), "=r"(r[3]) : "r"(addr));
}
__device__ __forceinline__ void ldsm_x2(uint32_t* r, uint32_t addr) {
    asm volatile("ldmatrix.sync.aligned.m8n8.x2.shared.b16 {%0,%1}, [%2];"
                 : "=r"(r[0]), "=r"(r[1]) : "r"(addr));
}
__device__ __forceinline__ void nsleep() { asm volatile("nanosleep.u32 40;"); }

__device__ __forceinline__ float sigf(float v) { return 1.0f / (1.0f + __expf(-v)); }
__device__ __forceinline__ float tanhf_fast(float v) {
    float e = __expf(-2.0f * fabsf(v));
    float r = (1.0f - e) / (1.0f + e);
    return (v >= 0.0f) ? r : -r;
}

// ---------------------------------------------------------------------------
// Prep kernels
// ---------------------------------------------------------------------------
__global__ void split_x_kernel(const float* __restrict__ x) {
    size_t total = (size_t)Tt * Bb * Hh;
    size_t stride = (size_t)gridDim.x * blockDim.x;
    for (size_t i = (size_t)blockIdx.x * blockDim.x + threadIdx.x; i < total; i += stride) {
        float v = x[i];
        __nv_bfloat16 hi = __float2bfloat16(v);
        g_x_hi[i] = hi;
        g_x_lo[i] = __float2bfloat16(v - __bfloat162float(hi));
    }
}

__global__ void repack_kernel(const float* __restrict__ Wi, const float* __restrict__ Wf,
                              const float* __restrict__ Wc, const float* __restrict__ Wo,
                              const float* __restrict__ bi, const float* __restrict__ bf,
                              const float* __restrict__ bc, const float* __restrict__ bo) {
    size_t total = (size_t)G4 * K2;
    size_t stride = (size_t)gridDim.x * blockDim.x;
    for (size_t idx = (size_t)blockIdx.x * blockDim.x + threadIdx.x; idx < total; idx += stride) {
        int j = (int)(idx / K2);
        int k = (int)(idx % K2);
        int u = j >> 2, g = j & 3;
        const float* src = (g == 0) ? Wi : (g == 1) ? Wf : (g == 2) ? Wc : Wo;
        float v = src[(size_t)u * K2 + k];
        __nv_bfloat16 hi = __float2bfloat16(v);
        __nv_bfloat16 lo = __float2bfloat16(v - __bfloat162float(hi));
        if (k < Hh) {
            g_Wx_hi[(size_t)j * Hh + k] = hi;
            g_Wx_lo[(size_t)j * Hh + k] = lo;
        } else {
            g_Wh_hi[(size_t)j * Hh + (k - Hh)] = hi;
            g_Wh_lo[(size_t)j * Hh + (k - Hh)] = lo;
        }
    }
    for (int j = blockIdx.x * blockDim.x + threadIdx.x; j < G4; j += (int)stride) {
        int u = j >> 2, g = j & 3;
        const float* sb = (g == 0) ? bi : (g == 1) ? bf : (g == 2) ? bc : bo;
        g_bias[j] = sb[u];
    }
}

__global__ void init_state_kernel() {
    int i = blockIdx.x * blockDim.x + threadIdx.x;
    int stride = gridDim.x * blockDim.x;
    __nv_bfloat16 z = __float2bfloat16(0.0f);
    for (int k = i; k < Bb * Hh; k += stride) {
        g_hb_hi[0][k] = z; g_hb_hi[1][k] = z;
        g_hb_lo[0][k] = z; g_hb_lo[1][k] = z;
    }
    if (i == 0) g_ctr = 0u;
}

// ---------------------------------------------------------------------------
// x-GEMM via mma.sync + ldmatrix: gx = x @ Wx^T + b, bf16 hi/lo 3-product.
// CTA 128x128, 8 warps (2m x 4n), warp tile 64x32. K chunks of 64, 2-buffer.
// ---------------------------------------------------------------------------
#define RS 72
#define ARR (128 * RS * 2)
#define GX_SMEM (2 * 4 * ARR)

__global__ __launch_bounds__(256) void gemm_x_mma() {
    extern __shared__ char smem[];
    const uint32_t sbase = smem_u32(smem);
    const int tid = threadIdx.x;
    const int w = tid >> 5;
    const int lane = tid & 31;
    const int g = lane >> 2;
    const int t = lane & 3;
    const int n0 = blockIdx.x * 128;
    const int m0 = blockIdx.y * 128;
    const int wm = (w >> 2) * 64;
    const int wn = (w & 3) * 32;
    const int lrow = (lane & 7) + ((lane >> 3) & 1) * 8;
    const int lcol = (lane >> 4) * 8;

    const __nv_bfloat16* __restrict__ xh = g_x_hi;
    const __nv_bfloat16* __restrict__ xl = g_x_lo;
    const __nv_bfloat16* __restrict__ wh = g_Wx_hi;
    const __nv_bfloat16* __restrict__ wl = g_Wx_lo;

    auto stage = [&](int ch, int b) {
        uint32_t base = sbase + b * 4 * ARR;
#pragma unroll
        for (int it = 0; it < 4; it++) {
            int idx = it * 256 + tid;
            int r = idx >> 3;
            int s = idx & 7;
            uint32_t doff = (uint32_t)(r * RS + s * 8) * 2;
            size_t asrc = (size_t)(m0 + r) * Hh + ch * 64 + s * 8;
            size_t bsrc = (size_t)(n0 + r) * Hh + ch * 64 + s * 8;
            cp16(base + 0 * ARR + doff, xh + asrc);
            cp16(base + 1 * ARR + doff, xl + asrc);
            cp16(base + 2 * ARR + doff, wh + bsrc);
            cp16(base + 3 * ARR + doff, wl + bsrc);
        }
        CP_COMMIT();
    };

    float C[4][4][4];
#pragma unroll
    for (int i = 0; i < 4; i++)
#pragma unroll
        for (int j = 0; j < 4; j++)
#pragma unroll
            for (int q = 0; q < 4; q++) C[i][j][q] = 0.0f;

    // per-warp ldmatrix byte offsets within an array
    const uint32_t a_off = (uint32_t)((wm + lrow) * RS + lcol) * 2;
    const uint32_t b_off = (uint32_t)((wn + lrow) * RS + lcol) * 2;

    stage(0, 0);
    for (int ch = 0; ch < 16; ch++) {
        if (ch < 15) stage(ch + 1, (ch + 1) & 1);
        if (ch < 15) cp_wait<1>(); else cp_wait<0>();
        __syncthreads();
        const uint32_t buf = sbase + (uint32_t)(ch & 1) * 4 * ARR;
#pragma unroll
        for (int kk = 0; kk < 64; kk += 16) {
            uint32_t ah[4][4], al[4][4], bh[2][4], bl[2][4];
#pragma unroll
            for (int mt = 0; mt < 4; mt++) {
                ldsm_x4(ah[mt], buf + 0 * ARR + a_off + (uint32_t)(mt * 16 * RS + kk) * 2);
                ldsm_x4(al[mt], buf + 1 * ARR + a_off + (uint32_t)(mt * 16 * RS + kk) * 2);
            }
#pragma unroll
            for (int p = 0; p < 2; p++) {
                ldsm_x4(bh[p], buf + 2 * ARR + b_off + (uint32_t)(p * 16 * RS + kk) * 2);
                ldsm_x4(bl[p], buf + 3 * ARR + b_off + (uint32_t)(p * 16 * RS + kk) * 2);
            }
#pragma unroll
            for (int mt = 0; mt < 4; mt++)
#pragma unroll
                for (int nt = 0; nt < 4; nt++) {
                    int p = nt >> 1, s = nt & 1;
                    mma16816b(C[mt][nt], ah[mt], bh[p][s], bh[p][s + 2]);
                    mma16816b(C[mt][nt], ah[mt], bl[p][s], bl[p][s + 2]);
                    mma16816b(C[mt][nt], al[mt], bh[p][s], bh[p][s + 2]);
                }
        }
        __syncthreads();
    }
#pragma unroll
    for (int mt = 0; mt < 4; mt++) {
        int row = m0 + wm + mt * 16 + g;
#pragma unroll
        for (int nt = 0; nt < 4; nt++) {
            int col = n0 + wn + nt * 8 + 2 * t;
            float2 bv = *reinterpret_cast<const float2*>(g_bias + col);
            float2 o0 = { C[mt][nt][0] + bv.x, C[mt][nt][1] + bv.y };
            float2 o1 = { C[mt][nt][2] + bv.x, C[mt][nt][3] + bv.y };
            *reinterpret_cast<float2*>(g_gx + (size_t)row * G4 + col) = o0;
            *reinterpret_cast<float2*>(g_gx + (size_t)(row + 8) * G4 + col) = o1;
        }
    }
}

// ---------------------------------------------------------------------------
// Persistent recurrent kernel: 128 blocks x 256 threads, all 512 steps.
// SMEM (bytes):
//   WH hi [32][1032]bf16 @ 0        (66048)
//   WH lo                @ 66048    (66048)
//   H ring: 4 bufs x { hi [64][72]bf16 (9216) + lo (9216) } @ 132096 (73728)
//   GXS [64][36]f32 @ 205824 (9216)  -> total 215040
// ---------------------------------------------------------------------------
#define WH_HI_OFF 0
#define WH_LO_OFF 66048
#define HB_OFF    132096
#define HCH_SZ    18432
#define HLO_SUB   9216
#define GXS_OFF   205824
#define PERSIST_SMEM 215040

__global__ __launch_bounds__(256, 1) void lstm_persist(float* __restrict__ out) {
    extern __shared__ char smem[];
    const uint32_t sbase = smem_u32(smem);
    const int tid = threadIdx.x;
    const int bu = blockIdx.x;
    const int w = tid >> 5;
    const int lane = tid & 31;
    const int g = lane >> 2;
    const int tq = lane & 3;
    const int wm = (w >> 2) * 32;   // 0 or 32
    const int wn = (w & 3) * 8;     // 0,8,16,24

    // ---- load Wh slice into smem (once) ----
    {
        const __nv_bfloat16* shi = g_Wh_hi + (size_t)bu * 32 * Hh;
        const __nv_bfloat16* slo = g_Wh_lo + (size_t)bu * 32 * Hh;
#pragma unroll
        for (int q = 0; q < 16; q++) {
            int idx = q * 256 + tid;
            int row = idx >> 7;
            int seg = idx & 127;
            uint32_t doff = (uint32_t)(row * 1032 + seg * 8) * 2;
            cp16(sbase + WH_HI_OFF + doff, shi + (size_t)row * Hh + seg * 8);
            cp16(sbase + WH_LO_OFF + doff, slo + (size_t)row * Hh + seg * 8);
        }
        CP_COMMIT();
        cp_wait<0>();
    }
    __syncthreads();

    const int lrow = (lane & 7) + ((lane >> 3) & 1) * 8;
    const int lcol = (lane >> 4) * 8;
    const uint32_t a_lane_off = (uint32_t)((wm + lrow) * 72 + lcol) * 2;
    const uint32_t b_lane_off = (uint32_t)((wn + (lane & 7)) * 1032 + ((lane >> 3) & 1) * 8) * 2;
    const uint32_t b_hi_base = sbase + WH_HI_OFF + b_lane_off;
    const uint32_t b_lo_base = sbase + WH_LO_OFF + b_lane_off;

    const int myMt = tq & 1;
    const int row0 = wm + myMt * 16 + g;
    const int row1 = row0 + 8;
    const int u_glob = bu * 8 + (wn >> 2) + (tq >> 1);

    float creg0 = 0.0f, creg1 = 0.0f;
    float hlast0 = 0.0f, hlast1 = 0.0f;
    const float* gxs = reinterpret_cast<const float*>(smem + GXS_OFF);

    for (int t = 0; t < Tt; t++) {
        const int par = t & 1;
        const __nv_bfloat16* hsrc_hi = g_hb_hi[par];
        const __nv_bfloat16* hsrc_lo = g_hb_lo[par];

        // gx prefetch: 64 rows x 32 cols fp32 (1 group)
        {
#pragma unroll
            for (int q = 0; q < 2; q++) {
                int idx = q * 256 + tid;
                int row = idx >> 3;
                int seg = idx & 7;
                cp16(sbase + GXS_OFF + (uint32_t)(row * 144 + seg * 16),
                     g_gx + ((size_t)t * Bb + row) * G4 + bu * 32 + seg * 4);
            }
            CP_COMMIT();
        }

        // h chunk staging: 64 cols per chunk, 4-buffer ring
        auto stage_h = [&](int ch) {
            uint32_t base = sbase + HB_OFF + (uint32_t)(ch & 3) * HCH_SZ;
#pragma unroll
            for (int q = 0; q < 4; q++) {
                int idx = q * 256 + tid;          // 0..1023
                int sel = idx >> 9;               // 0=hi, 1=lo
                int row = (idx >> 3) & 63;
                int seg = idx & 7;
                uint32_t doff = (uint32_t)(row * 72 + seg * 8) * 2 + (uint32_t)sel * HLO_SUB;
                const __nv_bfloat16* src = sel ? hsrc_lo : hsrc_hi;
                cp16(base + doff, src + (size_t)row * Hh + ch * 64 + seg * 8);
            }
            CP_COMMIT();
        };
        stage_h(0);
        stage_h(1);

        float C[2][4];
#pragma unroll
        for (int q = 0; q < 4; q++) { C[0][q] = 0.0f; C[1][q] = 0.0f; }

        for (int ch = 0; ch < 16; ch++) {
            if (ch < 14) { stage_h(ch + 2); cp_wait<2>(); }
            else if (ch == 14) cp_wait<1>();
            else cp_wait<0>();
            __syncthreads();

            const uint32_t abuf = sbase + HB_OFF + (uint32_t)(ch & 3) * HCH_SZ + a_lane_off;
            const uint32_t bco = (uint32_t)ch * 128;  // 64 cols * 2B

            uint32_t fa[2][2][4], fl[2][2][4], fb[2][2][2];
            // preload k16 = 0
            ldsm_x2(fb[0][0], b_hi_base + bco);
            ldsm_x2(fb[0][1], b_lo_base + bco);
            ldsm_x4(fa[0][0], abuf);
            ldsm_x4(fa[0][1], abuf + 2304);
            ldsm_x4(fl[0][0], abuf + HLO_SUB);
            ldsm_x4(fl[0][1], abuf + HLO_SUB + 2304);
#pragma unroll
            for (int k16 = 0; k16 < 4; k16++) {
                int cur = k16 & 1;
                if (k16 < 3) {
                    int nb = cur ^ 1;
                    uint32_t kb = (uint32_t)(k16 + 1) * 32;
                    ldsm_x2(fb[nb][0], b_hi_base + bco + kb);
                    ldsm_x2(fb[nb][1], b_lo_base + bco + kb);
                    ldsm_x4(fa[nb][0], abuf + kb);
                    ldsm_x4(fa[nb][1], abuf + 2304 + kb);
                    ldsm_x4(fl[nb][0], abuf + HLO_SUB + kb);
                    ldsm_x4(fl[nb][1], abuf + HLO_SUB + 2304 + kb);
                }
#pragma unroll
                for (int mt = 0; mt < 2; mt++) {
                    mma16816(C[mt], fa[cur][mt], fb[cur][0]);
                    mma16816(C[mt], fa[cur][mt], fb[cur][1]);
                    mma16816(C[mt], fl[cur][mt], fb[cur][0]);
                }
            }
        }

        // ---- epilogue ----
        float v[2][4], p[2][4];
#pragma unroll
        for (int mt = 0; mt < 2; mt++) {
            int r0 = wm + mt * 16 + g;
            int r1 = r0 + 8;
            int col = wn + 2 * tq;
            v[mt][0] = C[mt][0] + gxs[r0 * 36 + col];
            v[mt][1] = C[mt][1] + gxs[r0 * 36 + col + 1];
            v[mt][2] = C[mt][2] + gxs[r1 * 36 + col];
            v[mt][3] = C[mt][3] + gxs[r1 * 36 + col + 1];
        }
#pragma unroll
        for (int mt = 0; mt < 2; mt++)
#pragma unroll
            for (int q = 0; q < 4; q++)
                p[mt][q] = __shfl_xor_sync(0xffffffffu, v[mt][q], 1);

        float ii0, ff0, cc0, oo0, ii1, ff1, cc1, oo1;
        if (myMt == 0) {
            ii0 = v[0][0]; ff0 = v[0][1]; cc0 = p[0][0]; oo0 = p[0][1];
            ii1 = v[0][2]; ff1 = v[0][3]; cc1 = p[0][2]; oo1 = p[0][3];
        } else {
            ii0 = p[1][0]; ff0 = p[1][1]; cc0 = v[1][0]; oo0 = v[1][1];
            ii1 = p[1][2]; ff1 = p[1][3]; cc1 = v[1][2]; oo1 = v[1][3];
        }

        float cn0 = fmaf(sigf(ff0), creg0, sigf(ii0) * tanhf_fast(cc0));
        float cn1 = fmaf(sigf(ff1), creg1, sigf(ii1) * tanhf_fast(cc1));
        creg0 = cn0; creg1 = cn1;
        float hn0 = sigf(oo0) * tanhf_fast(cn0);
        float hn1 = sigf(oo1) * tanhf_fast(cn1);
        hlast0 = hn0; hlast1 = hn1;

        const int np = (t + 1) & 1;
        __nv_bfloat16 h0h = __float2bfloat16(hn0);
        __nv_bfloat16 h1h = __float2bfloat16(hn1);
        g_hb_hi[np][row0 * Hh + u_glob] = h0h;
        g_hb_hi[np][row1 * Hh + u_glob] = h1h;
        g_hb_lo[np][row0 * Hh + u_glob] = __float2bfloat16(hn0 - __bfloat162float(h0h));
        g_hb_lo[np][row1 * Hh + u_glob] = __float2bfloat16(hn1 - __bfloat162float(h1h));

        if (t + 1 < Tt) {
            // arrive: all h stores done block-wide (syncthreads observes them;
            // tid0's cumulative fence.gpu releases them), then counter bump.
            __syncthreads();
            if (tid == 0) { __threadfence(); atomicAdd(&g_ctr, 1u); }
            // hide out-seq stores behind the barrier wait
            out[(size_t)t * (Bb * Hh) + row0 * Hh + u_glob] = hn0;
            out[(size_t)t * (Bb * Hh) + row1 * Hh + u_glob] = hn1;
            if (tid == 0) {
                unsigned tgt = (unsigned)(t + 1) * NBLK;
                while (*(volatile unsigned*)&g_ctr < tgt) nsleep();
                __threadfence();
            }
            __syncthreads();
        } else {
            out[(size_t)t * (Bb * Hh) + row0 * Hh + u_glob] = hn0;
            out[(size_t)t * (Bb * Hh) + row1 * Hh + u_glob] = hn1;
        }
    }

    // final h_T, c_T
    size_t base = (size_t)Tt * Bb * Hh;
    out[base + row0 * Hh + u_glob] = hlast0;
    out[base + row1 * Hh + u_glob] = hlast1;
    out[base + Bb * Hh + row0 * Hh + u_glob] = creg0;
    out[base + Bb * Hh + row1 * Hh + u_glob] = creg1;
}

// ---------------------------------------------------------------------------
extern "C" void kernel_launch(void* const* d_in, const int* in_sizes, int n_in,
                              void* d_out, int out_size) {
    const float* x  = (const float*)d_in[0];
    const float* Wi = (const float*)d_in[1];
    const float* bi = (const float*)d_in[2];
    const float* Wf = (const float*)d_in[3];
    const float* bf = (const float*)d_in[4];
    const float* Wc = (const float*)d_in[5];
    const float* bc = (const float*)d_in[6];
    const float* Wo = (const float*)d_in[7];
    const float* bo = (const float*)d_in[8];
    float* out = (float*)d_out;

    cudaFuncSetAttribute(gemm_x_mma, cudaFuncAttributeMaxDynamicSharedMemorySize, GX_SMEM);
    cudaFuncSetAttribute(lstm_persist, cudaFuncAttributeMaxDynamicSharedMemorySize, PERSIST_SMEM);

    repack_kernel<<<512, 256>>>(Wi, Wf, Wc, Wo, bi, bf, bc, bo);
    split_x_kernel<<<1024, 256>>>(x);
    init_state_kernel<<<512, 256>>>();

    gemm_x_mma<<<dim3(G4 / 128, (Tt * Bb) / 128), 256, GX_SMEM>>>();

    lstm_persist<<<NBLK, 256, PERSIST_SMEM>>>(out);
}